// round 1
// baseline (speedup 1.0000x reference)
#include <cuda_runtime.h>

#define B_SZ  8192
#define D_SZ  256
#define H_SZ  8192
#define K_TOP 32

// Scratch (static device globals; no runtime allocation allowed)
__device__ float g_xs[B_SZ * D_SZ];                    // x - b_dec      (8 MB)
__device__ float g_pre[(size_t)B_SZ * H_SZ];           // pre_acts       (256 MB)
__device__ float g_tv[B_SZ * K_TOP];                   // top-k values
__device__ int   g_ti[B_SZ * K_TOP];                   // top-k indices

// ---------------------------------------------------------------------------
// Kernel 0: xs = x - b_dec (elementwise, float4)
// ---------------------------------------------------------------------------
__global__ void sub_bdec_kernel(const float* __restrict__ x,
                                const float* __restrict__ b_dec) {
    int i = blockIdx.x * blockDim.x + threadIdx.x;   // float4 index
    float4 xv = ((const float4*)x)[i];
    float4 bv = ((const float4*)b_dec)[i & (D_SZ / 4 - 1)];
    float4 r;
    r.x = xv.x - bv.x; r.y = xv.y - bv.y; r.z = xv.z - bv.z; r.w = xv.w - bv.w;
    ((float4*)g_xs)[i] = r;
}

// ---------------------------------------------------------------------------
// Kernel 1: pre_acts = relu(xs @ W_enc^T + b_enc)   [B, H] fp32 SGEMM (NT)
// 128x128 tile, BK=16, 8x8 per thread, 256 threads.
// ---------------------------------------------------------------------------
#define BM 128
#define BN 128
#define BK 16

__global__ __launch_bounds__(256)
void enc_gemm_kernel(const float* __restrict__ Wenc,
                     const float* __restrict__ b_enc) {
    __shared__ float As[BK * BM];
    __shared__ float Bs[BK * BN];

    const int tid = threadIdx.x;
    const int m0 = blockIdx.y * BM;
    const int n0 = blockIdx.x * BN;
    const int tm0 = (tid >> 4) * 8;
    const int tn0 = (tid & 15) * 8;

    float acc[8][8];
#pragma unroll
    for (int i = 0; i < 8; i++)
#pragma unroll
        for (int j = 0; j < 8; j++) acc[i][j] = 0.0f;

    const float* A = g_xs;

    for (int k0 = 0; k0 < D_SZ; k0 += BK) {
        // Load 128x16 of A and W_enc, stored transposed (k-major)
#pragma unroll
        for (int l = tid; l < 512; l += 256) {
            int row = l >> 2;
            int c   = l & 3;
            float4 va = *(const float4*)(A + (size_t)(m0 + row) * D_SZ + k0 + c * 4);
            As[(c * 4 + 0) * BM + row] = va.x;
            As[(c * 4 + 1) * BM + row] = va.y;
            As[(c * 4 + 2) * BM + row] = va.z;
            As[(c * 4 + 3) * BM + row] = va.w;
            float4 vb = *(const float4*)(Wenc + (size_t)(n0 + row) * D_SZ + k0 + c * 4);
            Bs[(c * 4 + 0) * BN + row] = vb.x;
            Bs[(c * 4 + 1) * BN + row] = vb.y;
            Bs[(c * 4 + 2) * BN + row] = vb.z;
            Bs[(c * 4 + 3) * BN + row] = vb.w;
        }
        __syncthreads();

#pragma unroll
        for (int k = 0; k < BK; k++) {
            float rm[8], rn[8];
            *(float4*)(rm)     = *(const float4*)(As + k * BM + tm0);
            *(float4*)(rm + 4) = *(const float4*)(As + k * BM + tm0 + 4);
            *(float4*)(rn)     = *(const float4*)(Bs + k * BN + tn0);
            *(float4*)(rn + 4) = *(const float4*)(Bs + k * BN + tn0 + 4);
#pragma unroll
            for (int i = 0; i < 8; i++)
#pragma unroll
                for (int j = 0; j < 8; j++)
                    acc[i][j] += rm[i] * rn[j];
        }
        __syncthreads();
    }

    // Epilogue: + b_enc, relu, store
    float be[8];
    *(float4*)(be)     = *(const float4*)(b_enc + n0 + tn0);
    *(float4*)(be + 4) = *(const float4*)(b_enc + n0 + tn0 + 4);

#pragma unroll
    for (int i = 0; i < 8; i++) {
        size_t off = (size_t)(m0 + tm0 + i) * H_SZ + n0 + tn0;
        float4 o0, o1;
        o0.x = fmaxf(acc[i][0] + be[0], 0.0f);
        o0.y = fmaxf(acc[i][1] + be[1], 0.0f);
        o0.z = fmaxf(acc[i][2] + be[2], 0.0f);
        o0.w = fmaxf(acc[i][3] + be[3], 0.0f);
        o1.x = fmaxf(acc[i][4] + be[4], 0.0f);
        o1.y = fmaxf(acc[i][5] + be[5], 0.0f);
        o1.z = fmaxf(acc[i][6] + be[6], 0.0f);
        o1.w = fmaxf(acc[i][7] + be[7], 0.0f);
        *(float4*)(g_pre + off)     = o0;
        *(float4*)(g_pre + off + 4) = o1;
    }
}

// ---------------------------------------------------------------------------
// Kernel 2: exact per-row top-32 via 4-pass 8-bit radix select (values >= 0,
// float bits monotonic). Zeros skipped (they contribute nothing to decode).
// One block of 256 threads per row; row cached in smem.
// ---------------------------------------------------------------------------
__global__ __launch_bounds__(256)
void topk_kernel() {
    __shared__ unsigned s_u[H_SZ];
    __shared__ int s_hist[256];
    __shared__ int s_scan[256];
    __shared__ int s_sel;
    __shared__ int s_short;
    __shared__ int s_cnt;

    const int tid = threadIdx.x;
    const int r = blockIdx.x;

    const float4* row4 = (const float4*)(g_pre + (size_t)r * H_SZ);
#pragma unroll
    for (int i = tid; i < H_SZ / 4; i += 256) {
        float4 v = row4[i];
        s_u[i * 4 + 0] = __float_as_uint(v.x);
        s_u[i * 4 + 1] = __float_as_uint(v.y);
        s_u[i * 4 + 2] = __float_as_uint(v.z);
        s_u[i * 4 + 3] = __float_as_uint(v.w);
    }
    if (tid < K_TOP) { g_tv[r * K_TOP + tid] = 0.0f; g_ti[r * K_TOP + tid] = 0; }
    if (tid == 0) { s_short = 0; s_sel = 0; }
    __syncthreads();

    unsigned prefix = 0;
    int krem = K_TOP;
    bool short_flag = false;

#pragma unroll 1
    for (int shift = 24; shift >= 0; shift -= 8) {
        s_hist[tid] = 0;
        __syncthreads();

        const unsigned pmask = (shift == 24) ? 0u : (0xFFFFFFFFu << (shift + 8));
#pragma unroll 1
        for (int j = 0; j < H_SZ / 256; j++) {
            unsigned u = s_u[tid + j * 256];
            if (u != 0u && (u & pmask) == prefix)
                atomicAdd(&s_hist[(u >> shift) & 255], 1);
        }
        __syncthreads();

        // suffix (from-top) inclusive scan: s_scan[i] = sum_{j>=i} hist[j]
        s_scan[tid] = s_hist[tid];
        __syncthreads();
#pragma unroll 1
        for (int off = 1; off < 256; off <<= 1) {
            int add = (tid + off < 256) ? s_scan[tid + off] : 0;
            __syncthreads();
            s_scan[tid] += add;
            __syncthreads();
        }

        if (tid == 0 && s_scan[0] < krem) s_short = 1;   // < krem candidates (only pass 1)
        int nxt = (tid < 255) ? s_scan[tid + 1] : 0;
        if (s_scan[tid] >= krem && nxt < krem) s_sel = tid;
        __syncthreads();

        if (s_short) { short_flag = true; break; }

        int b = s_sel;
        int above = (b < 255) ? s_scan[b + 1] : 0;
        krem -= above;
        prefix |= ((unsigned)b) << shift;
        __syncthreads();
    }

    const unsigned kth = short_flag ? 1u : prefix;  // short path: take every nonzero

    if (tid == 0) s_cnt = 0;
    __syncthreads();

    // strictly greater than kth first (count <= 31 by construction)
#pragma unroll 1
    for (int j = 0; j < H_SZ / 256; j++) {
        unsigned u = s_u[tid + j * 256];
        if (u > kth) {
            int p = atomicAdd(&s_cnt, 1);
            g_tv[r * K_TOP + p] = __uint_as_float(u);
            g_ti[r * K_TOP + p] = tid + j * 256;
        }
    }
    __syncthreads();

    // fill remaining slots with ties == kth
#pragma unroll 1
    for (int j = 0; j < H_SZ / 256; j++) {
        unsigned u = s_u[tid + j * 256];
        if (u == kth && u != 0u) {
            int p = atomicAdd(&s_cnt, 1);
            if (p < K_TOP) {
                g_tv[r * K_TOP + p] = __uint_as_float(u);
                g_ti[r * K_TOP + p] = tid + j * 256;
            }
        }
    }
}

// ---------------------------------------------------------------------------
// Kernel 3: sparse decode  out[b,:] = b_dec + sum_k tv_k * W_dec[ti_k, :]
// One block of 256 threads per row (D = 256).
// ---------------------------------------------------------------------------
__global__ __launch_bounds__(256)
void decode_kernel(const float* __restrict__ Wdec,
                   const float* __restrict__ b_dec,
                   float* __restrict__ out) {
    const int r = blockIdx.x;
    const int d = threadIdx.x;
    float acc = b_dec[d];
#pragma unroll
    for (int k = 0; k < K_TOP; k++) {
        float v  = g_tv[r * K_TOP + k];
        int   ix = g_ti[r * K_TOP + k];
        acc += v * __ldg(Wdec + (size_t)ix * D_SZ + d);
    }
    out[(size_t)r * D_SZ + d] = acc;
}

// ---------------------------------------------------------------------------
extern "C" void kernel_launch(void* const* d_in, const int* in_sizes, int n_in,
                              void* d_out, int out_size) {
    const float* x    = (const float*)d_in[0];
    const float* Wenc = (const float*)d_in[1];
    const float* benc = (const float*)d_in[2];
    const float* Wdec = (const float*)d_in[3];
    const float* bdec = (const float*)d_in[4];
    float* out = (float*)d_out;

    sub_bdec_kernel<<<(B_SZ * D_SZ / 4) / 256, 256>>>(x, bdec);

    dim3 grid(H_SZ / BN, B_SZ / BM);
    enc_gemm_kernel<<<grid, 256>>>(Wenc, benc);

    topk_kernel<<<B_SZ, 256>>>();

    decode_kernel<<<B_SZ, 256>>>(Wdec, bdec, out);
}

// round 3
// speedup vs baseline: 1.2561x; 1.2561x over previous
#include <cuda_runtime.h>
#include <cuda_bf16.h>
#include <cstdint>

#define B_SZ  8192
#define D_SZ  256
#define H_SZ  8192
#define K_TOP 32
#define KE    1536            // 6 limb-chunks * 256

// ---------------- scratch (static device globals) ----------------
__device__ float g_pre[(size_t)B_SZ * H_SZ];              // pre_acts (256 MB)
__device__ float g_tv[B_SZ * K_TOP];
__device__ int   g_ti[B_SZ * K_TOP];
__device__ __nv_bfloat16 g_A[(size_t)B_SZ * KE];          // 25 MB
__device__ __nv_bfloat16 g_B[(size_t)H_SZ * KE];          // 25 MB

// ---------------- helpers ----------------
__device__ __forceinline__ uint32_t smem_u32(const void* p) {
    uint32_t a;
    asm("{ .reg .u64 t; cvta.to.shared.u64 t, %1; cvt.u32.u64 %0, t; }" : "=r"(a) : "l"(p));
    return a;
}
__device__ __forceinline__ void cp_async16(uint32_t dst, const void* src) {
    asm volatile("cp.async.cg.shared.global [%0], [%1], 16;" :: "r"(dst), "l"(src));
}
#define CP_COMMIT() asm volatile("cp.async.commit_group;" ::: "memory")
#define CP_WAIT(n)  asm volatile("cp.async.wait_group %0;" :: "n"(n) : "memory")

__device__ __forceinline__ void ldsm4(uint32_t& r0, uint32_t& r1, uint32_t& r2, uint32_t& r3, uint32_t addr) {
    asm volatile("ldmatrix.sync.aligned.m8n8.x4.shared.b16 {%0,%1,%2,%3}, [%4];"
                 : "=r"(r0), "=r"(r1), "=r"(r2), "=r"(r3) : "r"(addr));
}
__device__ __forceinline__ void mma16816(float* d, const uint32_t* a, const uint32_t* b) {
    asm volatile("mma.sync.aligned.m16n8k16.row.col.f32.bf16.bf16.f32 "
                 "{%0,%1,%2,%3}, {%4,%5,%6,%7}, {%8,%9}, {%0,%1,%2,%3};"
                 : "+f"(d[0]), "+f"(d[1]), "+f"(d[2]), "+f"(d[3])
                 : "r"(a[0]), "r"(a[1]), "r"(a[2]), "r"(a[3]), "r"(b[0]), "r"(b[1]));
}

// ---------------------------------------------------------------------------
// Split kernels: 3-limb bf16 decomposition, written interleaved along K'.
// A' chunk t holds limb ta[t] of (x-b_dec); B' chunk t holds limb tb[t] of W.
// ta = {0,0,1,1,0,2},  tb = {0,1,0,1,2,0}
// ---------------------------------------------------------------------------
__device__ __forceinline__ void split3(float v, float& f0, float& f1, float& f2) {
    __nv_bfloat16 h0 = __float2bfloat16_rn(v);
    f0 = __bfloat162float(h0);
    float r1 = v - f0;
    __nv_bfloat16 h1 = __float2bfloat16_rn(r1);
    f1 = __bfloat162float(h1);
    f2 = r1 - f1;
}
__device__ __forceinline__ uint32_t packbf2(float lo, float hi) {
    __nv_bfloat162 h = __floats2bfloat162_rn(lo, hi);
    return *reinterpret_cast<uint32_t*>(&h);
}

__global__ void split_x_kernel(const float* __restrict__ x, const float* __restrict__ b_dec) {
    int i = blockIdx.x * blockDim.x + threadIdx.x;     // float4 index
    int m = i >> 6;                                    // 64 float4 per row
    int kq = (i & 63) * 4;
    float4 xv = ((const float4*)x)[i];
    float4 bv = ((const float4*)b_dec)[i & 63];
    float v[4] = {xv.x - bv.x, xv.y - bv.y, xv.z - bv.z, xv.w - bv.w};
    float l0[4], l1[4], l2[4];
#pragma unroll
    for (int j = 0; j < 4; j++) split3(v[j], l0[j], l1[j], l2[j]);
    uint2 p0 = {packbf2(l0[0], l0[1]), packbf2(l0[2], l0[3])};
    uint2 p1 = {packbf2(l1[0], l1[1]), packbf2(l1[2], l1[3])};
    uint2 p2 = {packbf2(l2[0], l2[1]), packbf2(l2[2], l2[3])};
    __nv_bfloat16* row = g_A + (size_t)m * KE + kq;
    *(uint2*)(row + 0 * 256) = p0;       // t0: a0
    *(uint2*)(row + 1 * 256) = p0;       // t1: a0
    *(uint2*)(row + 2 * 256) = p1;       // t2: a1
    *(uint2*)(row + 3 * 256) = p1;       // t3: a1
    *(uint2*)(row + 4 * 256) = p0;       // t4: a0
    *(uint2*)(row + 5 * 256) = p2;       // t5: a2
}

__global__ void split_w_kernel(const float* __restrict__ w) {
    int i = blockIdx.x * blockDim.x + threadIdx.x;
    int n = i >> 6;
    int kq = (i & 63) * 4;
    float4 wv = ((const float4*)w)[i];
    float v[4] = {wv.x, wv.y, wv.z, wv.w};
    float l0[4], l1[4], l2[4];
#pragma unroll
    for (int j = 0; j < 4; j++) split3(v[j], l0[j], l1[j], l2[j]);
    uint2 p0 = {packbf2(l0[0], l0[1]), packbf2(l0[2], l0[3])};
    uint2 p1 = {packbf2(l1[0], l1[1]), packbf2(l1[2], l1[3])};
    uint2 p2 = {packbf2(l2[0], l2[1]), packbf2(l2[2], l2[3])};
    __nv_bfloat16* row = g_B + (size_t)n * KE + kq;
    *(uint2*)(row + 0 * 256) = p0;       // t0: b0
    *(uint2*)(row + 1 * 256) = p1;       // t1: b1
    *(uint2*)(row + 2 * 256) = p0;       // t2: b0
    *(uint2*)(row + 3 * 256) = p1;       // t3: b1
    *(uint2*)(row + 4 * 256) = p2;       // t4: b2
    *(uint2*)(row + 5 * 256) = p0;       // t5: b0
}

// ---------------------------------------------------------------------------
// Encoder GEMM: pre = relu(A' @ B'^T + b_enc), bf16 mma.sync, K=1536.
// BM=128, BN=256, BK=32, 4-stage cp.async pipeline, 512 threads (16 warps 4x4).
// ---------------------------------------------------------------------------
#define BM 128
#define BN 256
#define GBK 32
#define STAGES 4
#define KT (KE / GBK)                       // 48
#define A_ST_BYTES (BM * GBK * 2)           // 8192
#define B_ST_BYTES (BN * GBK * 2)           // 16384
#define ST_BYTES   (A_ST_BYTES + B_ST_BYTES)
#define SMEM_GEMM  (STAGES * ST_BYTES)      // 98304

// swizzled 16B-chunk offset within a [rows][32] bf16 tile (64B rows)
__device__ __forceinline__ uint32_t sw_off(int row, int c) {
    return (uint32_t)(row * 64 + ((c ^ ((row >> 1) & 3)) << 4));
}

__device__ __forceinline__ void stage_load(uint32_t sbase, int st, int kt, int tid,
                                           const __nv_bfloat16* gA, const __nv_bfloat16* gB) {
    uint32_t sa = sbase + st * ST_BYTES;
    uint32_t sb = sa + A_ST_BYTES;
    int k0 = kt * GBK;
    {
        int row = tid >> 2, c = tid & 3;
        cp_async16(sa + sw_off(row, c), gA + (size_t)row * KE + k0 + c * 8);
    }
#pragma unroll
    for (int i = 0; i < 2; i++) {
        int idx = tid + i * 512;
        int row = idx >> 2, c = idx & 3;
        cp_async16(sb + sw_off(row, c), gB + (size_t)row * KE + k0 + c * 8);
    }
}

__global__ __launch_bounds__(512, 1)
void enc_mma_kernel(const float* __restrict__ b_enc) {
    extern __shared__ char smem[];
    __shared__ float s_be[BN];

    const uint32_t sbase = smem_u32(smem);
    const int tid = threadIdx.x;
    const int wid = tid >> 5, lid = tid & 31;
    const int n0 = blockIdx.x * BN;
    const int m0 = blockIdx.y * BM;
    const int wm = (wid & 3) * 32;           // warp M offset (2 m16 tiles)
    const int wn = (wid >> 2) * 64;          // warp N offset (8 n8 tiles)

    if (tid < BN) s_be[tid] = b_enc[n0 + tid];

    const __nv_bfloat16* gA = g_A + (size_t)m0 * KE;
    const __nv_bfloat16* gB = g_B + (size_t)n0 * KE;

    float d[2][8][4];
#pragma unroll
    for (int mt = 0; mt < 2; mt++)
#pragma unroll
        for (int nt = 0; nt < 8; nt++)
#pragma unroll
            for (int j = 0; j < 4; j++) d[mt][nt][j] = 0.0f;

#pragma unroll
    for (int s = 0; s < STAGES - 1; s++) { stage_load(sbase, s, s, tid, gA, gB); CP_COMMIT(); }

    const int g  = lid >> 3;                  // ldmatrix group 0..3
    const int lr = lid & 7;

#pragma unroll 1
    for (int kt = 0; kt < KT; kt++) {
        CP_WAIT(2);
        __syncthreads();
        const int st = kt & (STAGES - 1);
        const uint32_t sa = sbase + st * ST_BYTES;
        const uint32_t sb = sa + A_ST_BYTES;

        if (kt + STAGES - 1 < KT)
            stage_load(sbase, (kt + STAGES - 1) & (STAGES - 1), kt + STAGES - 1, tid, gA, gB);
        CP_COMMIT();

#pragma unroll
        for (int ks = 0; ks < 2; ks++) {
            uint32_t a[2][4], b[4][4];
#pragma unroll
            for (int mt = 0; mt < 2; mt++) {
                int row = wm + mt * 16 + (g & 1) * 8 + lr;
                int c   = ks * 2 + (g >> 1);
                ldsm4(a[mt][0], a[mt][1], a[mt][2], a[mt][3], sa + sw_off(row, c));
            }
#pragma unroll
            for (int np = 0; np < 4; np++) {
                int row = wn + (np * 2 + (g >> 1)) * 8 + lr;
                int c   = ks * 2 + (g & 1);
                ldsm4(b[np][0], b[np][1], b[np][2], b[np][3], sb + sw_off(row, c));
            }
#pragma unroll
            for (int mt = 0; mt < 2; mt++)
#pragma unroll
                for (int nt = 0; nt < 8; nt++)
                    mma16816(d[mt][nt], a[mt], &b[nt >> 1][(nt & 1) * 2]);
        }
        __syncthreads();
    }

    // Epilogue: bias + relu + store fp32
#pragma unroll
    for (int mt = 0; mt < 2; mt++) {
        int row0 = m0 + wm + mt * 16 + (lid >> 2);
#pragma unroll
        for (int nt = 0; nt < 8; nt++) {
            int coll = wn + nt * 8 + (lid & 3) * 2;     // local col in [0,256)
            float be0 = s_be[coll], be1 = s_be[coll + 1];
            float2 o0, o1;
            o0.x = fmaxf(d[mt][nt][0] + be0, 0.0f);
            o0.y = fmaxf(d[mt][nt][1] + be1, 0.0f);
            o1.x = fmaxf(d[mt][nt][2] + be0, 0.0f);
            o1.y = fmaxf(d[mt][nt][3] + be1, 0.0f);
            *(float2*)(g_pre + (size_t)row0 * H_SZ + n0 + coll)       = o0;
            *(float2*)(g_pre + (size_t)(row0 + 8) * H_SZ + n0 + coll) = o1;
        }
    }
}

// ---------------------------------------------------------------------------
// Top-32 per row: 4-pass 8-bit radix select (unchanged from R1, passing)
// ---------------------------------------------------------------------------
__global__ __launch_bounds__(256)
void topk_kernel() {
    __shared__ unsigned s_u[H_SZ];
    __shared__ int s_hist[256];
    __shared__ int s_scan[256];
    __shared__ int s_sel;
    __shared__ int s_short;
    __shared__ int s_cnt;

    const int tid = threadIdx.x;
    const int r = blockIdx.x;

    const float4* row4 = (const float4*)(g_pre + (size_t)r * H_SZ);
#pragma unroll
    for (int i = tid; i < H_SZ / 4; i += 256) {
        float4 v = row4[i];
        s_u[i * 4 + 0] = __float_as_uint(v.x);
        s_u[i * 4 + 1] = __float_as_uint(v.y);
        s_u[i * 4 + 2] = __float_as_uint(v.z);
        s_u[i * 4 + 3] = __float_as_uint(v.w);
    }
    if (tid < K_TOP) { g_tv[r * K_TOP + tid] = 0.0f; g_ti[r * K_TOP + tid] = 0; }
    if (tid == 0) { s_short = 0; s_sel = 0; }
    __syncthreads();

    unsigned prefix = 0;
    int krem = K_TOP;
    bool short_flag = false;

#pragma unroll 1
    for (int shift = 24; shift >= 0; shift -= 8) {
        s_hist[tid] = 0;
        __syncthreads();

        const unsigned pmask = (shift == 24) ? 0u : (0xFFFFFFFFu << (shift + 8));
#pragma unroll 1
        for (int j = 0; j < H_SZ / 256; j++) {
            unsigned u = s_u[tid + j * 256];
            if (u != 0u && (u & pmask) == prefix)
                atomicAdd(&s_hist[(u >> shift) & 255], 1);
        }
        __syncthreads();

        s_scan[tid] = s_hist[tid];
        __syncthreads();
#pragma unroll 1
        for (int off = 1; off < 256; off <<= 1) {
            int add = (tid + off < 256) ? s_scan[tid + off] : 0;
            __syncthreads();
            s_scan[tid] += add;
            __syncthreads();
        }

        if (tid == 0 && s_scan[0] < krem) s_short = 1;
        int nxt = (tid < 255) ? s_scan[tid + 1] : 0;
        if (s_scan[tid] >= krem && nxt < krem) s_sel = tid;
        __syncthreads();

        if (s_short) { short_flag = true; break; }

        int b = s_sel;
        int above = (b < 255) ? s_scan[b + 1] : 0;
        krem -= above;
        prefix |= ((unsigned)b) << shift;
        __syncthreads();
    }

    const unsigned kth = short_flag ? 1u : prefix;

    if (tid == 0) s_cnt = 0;
    __syncthreads();

#pragma unroll 1
    for (int j = 0; j < H_SZ / 256; j++) {
        unsigned u = s_u[tid + j * 256];
        if (u > kth) {
            int p = atomicAdd(&s_cnt, 1);
            g_tv[r * K_TOP + p] = __uint_as_float(u);
            g_ti[r * K_TOP + p] = tid + j * 256;
        }
    }
    __syncthreads();

#pragma unroll 1
    for (int j = 0; j < H_SZ / 256; j++) {
        unsigned u = s_u[tid + j * 256];
        if (u == kth && u != 0u) {
            int p = atomicAdd(&s_cnt, 1);
            if (p < K_TOP) {
                g_tv[r * K_TOP + p] = __uint_as_float(u);
                g_ti[r * K_TOP + p] = tid + j * 256;
            }
        }
    }
}

// ---------------------------------------------------------------------------
// Sparse decode (unchanged from R1)
// ---------------------------------------------------------------------------
__global__ __launch_bounds__(256)
void decode_kernel(const float* __restrict__ Wdec,
                   const float* __restrict__ b_dec,
                   float* __restrict__ out) {
    const int r = blockIdx.x;
    const int d = threadIdx.x;
    float acc = b_dec[d];
#pragma unroll
    for (int k = 0; k < K_TOP; k++) {
        float v  = g_tv[r * K_TOP + k];
        int   ix = g_ti[r * K_TOP + k];
        acc += v * __ldg(Wdec + (size_t)ix * D_SZ + d);
    }
    out[(size_t)r * D_SZ + d] = acc;
}

// ---------------------------------------------------------------------------
extern "C" void kernel_launch(void* const* d_in, const int* in_sizes, int n_in,
                              void* d_out, int out_size) {
    const float* x    = (const float*)d_in[0];
    const float* Wenc = (const float*)d_in[1];
    const float* benc = (const float*)d_in[2];
    const float* Wdec = (const float*)d_in[3];
    const float* bdec = (const float*)d_in[4];
    float* out = (float*)d_out;

    split_x_kernel<<<(B_SZ * D_SZ / 4) / 256, 256>>>(x, bdec);
    split_w_kernel<<<(H_SZ * D_SZ / 4) / 256, 256>>>(Wenc);

    static bool attr_set = false;
    if (!attr_set) {
        cudaFuncSetAttribute(enc_mma_kernel, cudaFuncAttributeMaxDynamicSharedMemorySize, SMEM_GEMM);
        attr_set = true;
    }
    dim3 grid(H_SZ / BN, B_SZ / BM);
    enc_mma_kernel<<<grid, 512, SMEM_GEMM>>>(benc);

    topk_kernel<<<B_SZ, 256>>>();

    decode_kernel<<<B_SZ, 256>>>(Wdec, bdec, out);
}

// round 5
// speedup vs baseline: 2.1327x; 1.6979x over previous
#include <cuda_runtime.h>
#include <cuda_fp16.h>
#include <cstdint>

#define B_SZ  8192
#define D_SZ  256
#define H_SZ  8192
#define K_TOP 32
#define KE    768             // 3 limb-chunks * 256 (fp16 2-limb, 3 cross terms)

// ---------------- scratch (static device globals) ----------------
__device__ float g_pre[(size_t)B_SZ * H_SZ];              // pre_acts (256 MB)
__device__ float g_tv[B_SZ * K_TOP];
__device__ int   g_ti[B_SZ * K_TOP];
__device__ __half g_A[(size_t)B_SZ * KE];                 // 12.6 MB
__device__ __half g_B[(size_t)H_SZ * KE];                 // 12.6 MB

// ---------------- helpers ----------------
__device__ __forceinline__ uint32_t smem_u32(const void* p) {
    uint32_t a;
    asm("{ .reg .u64 t; cvta.to.shared.u64 t, %1; cvt.u32.u64 %0, t; }" : "=r"(a) : "l"(p));
    return a;
}
__device__ __forceinline__ void cp_async16(uint32_t dst, const void* src) {
    asm volatile("cp.async.cg.shared.global [%0], [%1], 16;" :: "r"(dst), "l"(src));
}
#define CP_COMMIT() asm volatile("cp.async.commit_group;" ::: "memory")
#define CP_WAIT(n)  asm volatile("cp.async.wait_group %0;" :: "n"(n) : "memory")

__device__ __forceinline__ void ldsm4(uint32_t& r0, uint32_t& r1, uint32_t& r2, uint32_t& r3, uint32_t addr) {
    asm volatile("ldmatrix.sync.aligned.m8n8.x4.shared.b16 {%0,%1,%2,%3}, [%4];"
                 : "=r"(r0), "=r"(r1), "=r"(r2), "=r"(r3) : "r"(addr));
}
__device__ __forceinline__ void mma16816(float* d, const uint32_t* a, const uint32_t* b) {
    asm volatile("mma.sync.aligned.m16n8k16.row.col.f32.f16.f16.f32 "
                 "{%0,%1,%2,%3}, {%4,%5,%6,%7}, {%8,%9}, {%0,%1,%2,%3};"
                 : "+f"(d[0]), "+f"(d[1]), "+f"(d[2]), "+f"(d[3])
                 : "r"(a[0]), "r"(a[1]), "r"(a[2]), "r"(a[3]), "r"(b[0]), "r"(b[1]));
}

// ---------------------------------------------------------------------------
// Split kernels: 2-limb fp16 decomposition, interleaved along K'.
// A' = [a0 | a0 | a1],  B' = [b0 | b1 | b0]  -> terms a0b0 + a0b1 + a1b0.
// ---------------------------------------------------------------------------
__device__ __forceinline__ uint32_t packh2(__half lo, __half hi) {
    __half2 h = __halves2half2(lo, hi);
    return *reinterpret_cast<uint32_t*>(&h);
}

__global__ void split_x_kernel(const float* __restrict__ x, const float* __restrict__ b_dec) {
    int i = blockIdx.x * blockDim.x + threadIdx.x;     // float4 index
    int m = i >> 6;
    int kq = (i & 63) * 4;
    float4 xv = ((const float4*)x)[i];
    float4 bv = ((const float4*)b_dec)[i & 63];
    float v[4] = {xv.x - bv.x, xv.y - bv.y, xv.z - bv.z, xv.w - bv.w};
    __half h0[4], h1[4];
#pragma unroll
    for (int j = 0; j < 4; j++) {
        h0[j] = __float2half_rn(v[j]);
        h1[j] = __float2half_rn(v[j] - __half2float(h0[j]));
    }
    uint2 p0 = {packh2(h0[0], h0[1]), packh2(h0[2], h0[3])};
    uint2 p1 = {packh2(h1[0], h1[1]), packh2(h1[2], h1[3])};
    __half* row = g_A + (size_t)m * KE + kq;
    *(uint2*)(row + 0 * 256) = p0;       // a0
    *(uint2*)(row + 1 * 256) = p0;       // a0
    *(uint2*)(row + 2 * 256) = p1;       // a1
}

__global__ void split_w_kernel(const float* __restrict__ w) {
    int i = blockIdx.x * blockDim.x + threadIdx.x;
    int n = i >> 6;
    int kq = (i & 63) * 4;
    float4 wv = ((const float4*)w)[i];
    float v[4] = {wv.x, wv.y, wv.z, wv.w};
    __half h0[4], h1[4];
#pragma unroll
    for (int j = 0; j < 4; j++) {
        h0[j] = __float2half_rn(v[j]);
        h1[j] = __float2half_rn(v[j] - __half2float(h0[j]));
    }
    uint2 p0 = {packh2(h0[0], h0[1]), packh2(h0[2], h0[3])};
    uint2 p1 = {packh2(h1[0], h1[1]), packh2(h1[2], h1[3])};
    __half* row = g_B + (size_t)n * KE + kq;
    *(uint2*)(row + 0 * 256) = p0;       // b0
    *(uint2*)(row + 1 * 256) = p1;       // b1
    *(uint2*)(row + 2 * 256) = p0;       // b0
}

// ---------------------------------------------------------------------------
// Encoder GEMM: pre = relu(A' @ B'^T + b_enc), fp16 mma.sync, K=768.
// ---------------------------------------------------------------------------
#define BM 128
#define BN 256
#define GBK 32
#define STAGES 4
#define KT (KE / GBK)                       // 24
#define A_ST_BYTES (BM * GBK * 2)
#define B_ST_BYTES (BN * GBK * 2)
#define ST_BYTES   (A_ST_BYTES + B_ST_BYTES)
#define SMEM_GEMM  (STAGES * ST_BYTES)      // 98304

__device__ __forceinline__ uint32_t sw_off(int row, int c) {
    return (uint32_t)(row * 64 + ((c ^ ((row >> 1) & 3)) << 4));
}

__device__ __forceinline__ void stage_load(uint32_t sbase, int st, int kt, int tid,
                                           const __half* gA, const __half* gB) {
    uint32_t sa = sbase + st * ST_BYTES;
    uint32_t sb = sa + A_ST_BYTES;
    int k0 = kt * GBK;
    {
        int row = tid >> 2, c = tid & 3;
        cp_async16(sa + sw_off(row, c), gA + (size_t)row * KE + k0 + c * 8);
    }
#pragma unroll
    for (int i = 0; i < 2; i++) {
        int idx = tid + i * 512;
        int row = idx >> 2, c = idx & 3;
        cp_async16(sb + sw_off(row, c), gB + (size_t)row * KE + k0 + c * 8);
    }
}

__global__ __launch_bounds__(512, 1)
void enc_mma_kernel(const float* __restrict__ b_enc) {
    extern __shared__ char smem[];
    __shared__ float s_be[BN];

    const uint32_t sbase = smem_u32(smem);
    const int tid = threadIdx.x;
    const int wid = tid >> 5, lid = tid & 31;
    const int n0 = blockIdx.x * BN;
    const int m0 = blockIdx.y * BM;
    const int wm = (wid & 3) * 32;
    const int wn = (wid >> 2) * 64;

    if (tid < BN) s_be[tid] = b_enc[n0 + tid];

    const __half* gA = g_A + (size_t)m0 * KE;
    const __half* gB = g_B + (size_t)n0 * KE;

    float d[2][8][4];
#pragma unroll
    for (int mt = 0; mt < 2; mt++)
#pragma unroll
        for (int nt = 0; nt < 8; nt++)
#pragma unroll
            for (int j = 0; j < 4; j++) d[mt][nt][j] = 0.0f;

#pragma unroll
    for (int s = 0; s < STAGES - 1; s++) { stage_load(sbase, s, s, tid, gA, gB); CP_COMMIT(); }

    const int g  = lid >> 3;
    const int lr = lid & 7;

#pragma unroll 1
    for (int kt = 0; kt < KT; kt++) {
        CP_WAIT(2);
        __syncthreads();
        const int st = kt & (STAGES - 1);
        const uint32_t sa = sbase + st * ST_BYTES;
        const uint32_t sb = sa + A_ST_BYTES;

        if (kt + STAGES - 1 < KT)
            stage_load(sbase, (kt + STAGES - 1) & (STAGES - 1), kt + STAGES - 1, tid, gA, gB);
        CP_COMMIT();

#pragma unroll
        for (int ks = 0; ks < 2; ks++) {
            uint32_t a[2][4], b[4][4];
#pragma unroll
            for (int mt = 0; mt < 2; mt++) {
                int row = wm + mt * 16 + (g & 1) * 8 + lr;
                int c   = ks * 2 + (g >> 1);
                ldsm4(a[mt][0], a[mt][1], a[mt][2], a[mt][3], sa + sw_off(row, c));
            }
#pragma unroll
            for (int np = 0; np < 4; np++) {
                int row = wn + (np * 2 + (g >> 1)) * 8 + lr;
                int c   = ks * 2 + (g & 1);
                ldsm4(b[np][0], b[np][1], b[np][2], b[np][3], sb + sw_off(row, c));
            }
#pragma unroll
            for (int mt = 0; mt < 2; mt++)
#pragma unroll
                for (int nt = 0; nt < 8; nt++)
                    mma16816(d[mt][nt], a[mt], &b[nt >> 1][(nt & 1) * 2]);
        }
        __syncthreads();
    }

#pragma unroll
    for (int mt = 0; mt < 2; mt++) {
        int row0 = m0 + wm + mt * 16 + (lid >> 2);
#pragma unroll
        for (int nt = 0; nt < 8; nt++) {
            int coll = wn + nt * 8 + (lid & 3) * 2;
            float be0 = s_be[coll], be1 = s_be[coll + 1];
            float2 o0, o1;
            o0.x = fmaxf(d[mt][nt][0] + be0, 0.0f);
            o0.y = fmaxf(d[mt][nt][1] + be1, 0.0f);
            o1.x = fmaxf(d[mt][nt][2] + be0, 0.0f);
            o1.y = fmaxf(d[mt][nt][3] + be1, 0.0f);
            *(float2*)(g_pre + (size_t)row0 * H_SZ + n0 + coll)       = o0;
            *(float2*)(g_pre + (size_t)(row0 + 8) * H_SZ + n0 + coll) = o1;
        }
    }
}

// ---------------------------------------------------------------------------
// Top-32: row in registers; 11-bit histogram prefilter, winners direct,
// candidates refined by 3x7-bit radix on a tiny smem list. Exact.
// ---------------------------------------------------------------------------
#define HBINS 2048
#define CAP   2048

__global__ __launch_bounds__(256)
void topk_kernel() {
    __shared__ int s_hist[HBINS];
    __shared__ int s_scan[256];
    __shared__ unsigned s_cu[CAP];
    __shared__ int s_ci[CAP];
    __shared__ int s_B1, s_above, s_cnt, s_ccnt, s_sel;

    const int tid = threadIdx.x;
    const int r = blockIdx.x;

    unsigned u[32];
    const float4* row4 = (const float4*)(g_pre + (size_t)r * H_SZ);
#pragma unroll
    for (int j = 0; j < 8; j++) {
        float4 v = row4[tid + j * 256];
        u[j * 4 + 0] = __float_as_uint(v.x);
        u[j * 4 + 1] = __float_as_uint(v.y);
        u[j * 4 + 2] = __float_as_uint(v.z);
        u[j * 4 + 3] = __float_as_uint(v.w);
    }

    if (tid < K_TOP) { g_tv[r * K_TOP + tid] = 0.0f; g_ti[r * K_TOP + tid] = 0; }
#pragma unroll
    for (int i = tid; i < HBINS; i += 256) s_hist[i] = 0;
    if (tid == 0) { s_B1 = -1; s_above = 0; s_cnt = 0; s_ccnt = 0; }
    __syncthreads();

#pragma unroll
    for (int j = 0; j < 32; j++)
        if (u[j]) atomicAdd(&s_hist[u[j] >> 21], 1);
    __syncthreads();

    int local = 0;
#pragma unroll
    for (int b = 0; b < 8; b++) local += s_hist[tid * 8 + b];
    s_scan[tid] = local;
    __syncthreads();
#pragma unroll 1
    for (int off = 1; off < 256; off <<= 1) {
        int add = (tid + off < 256) ? s_scan[tid + off] : 0;
        __syncthreads();
        s_scan[tid] += add;
        __syncthreads();
    }
    const int total = s_scan[0];
    {
        int run = s_scan[tid] - local;
#pragma unroll
        for (int b = 7; b >= 0; b--) {
            int h = s_hist[tid * 8 + b];
            if (run < K_TOP && run + h >= K_TOP) { s_B1 = tid * 8 + b; s_above = run; }
            run += h;
        }
    }
    __syncthreads();

    if (total < K_TOP) {
#pragma unroll
        for (int j = 0; j < 32; j++) {
            if (u[j]) {
                int idx = (tid + (j >> 2) * 256) * 4 + (j & 3);
                int p = atomicAdd(&s_cnt, 1);
                g_tv[r * K_TOP + p] = __uint_as_float(u[j]);
                g_ti[r * K_TOP + p] = idx;
            }
        }
        return;
    }

    const int B1 = s_B1;

#pragma unroll
    for (int j = 0; j < 32; j++) {
        int idx = (tid + (j >> 2) * 256) * 4 + (j & 3);
        unsigned key = u[j] >> 21;
        if (u[j] && (int)key > B1) {
            int p = atomicAdd(&s_cnt, 1);
            g_tv[r * K_TOP + p] = __uint_as_float(u[j]);
            g_ti[r * K_TOP + p] = idx;
        } else if (u[j] && (int)key == B1) {
            int p = atomicAdd(&s_ccnt, 1);
            if (p < CAP) { s_cu[p] = u[j] & 0x1FFFFFu; s_ci[p] = idx; }
        }
    }
    __syncthreads();

    const int above = s_above;
    int krem = K_TOP - above;
    int ccnt = s_ccnt < CAP ? s_ccnt : CAP;

    if (ccnt <= krem) {
        for (int i = tid; i < ccnt; i += 256) {
            int p = atomicAdd(&s_cnt, 1);
            g_tv[r * K_TOP + p] = __uint_as_float(((unsigned)B1 << 21) | s_cu[i]);
            g_ti[r * K_TOP + p] = s_ci[i];
        }
        return;
    }

    unsigned prefix21 = 0;
#pragma unroll 1
    for (int shift = 14; shift >= 0; shift -= 7) {
        if (tid < 128) s_hist[tid] = 0;
        if (tid == 0) s_sel = 0;
        __syncthreads();
        unsigned pmask = (shift == 14) ? 0u : ((0x1FFFFFu << (shift + 7)) & 0x1FFFFFu);
        for (int i = tid; i < ccnt; i += 256) {
            unsigned cu = s_cu[i];
            if ((cu & pmask) == prefix21) atomicAdd(&s_hist[(cu >> shift) & 127], 1);
        }
        __syncthreads();
        if (tid < 128) s_scan[tid] = s_hist[tid];
        __syncthreads();
#pragma unroll 1
        for (int off = 1; off < 128; off <<= 1) {
            int add = (tid < 128 && tid + off < 128) ? s_scan[tid + off] : 0;
            __syncthreads();
            if (tid < 128) s_scan[tid] += add;
            __syncthreads();
        }
        if (tid < 128) {
            int nxt = (tid < 127) ? s_scan[tid + 1] : 0;
            if (s_scan[tid] >= krem && nxt < krem) s_sel = tid;
        }
        __syncthreads();
        int dsel = s_sel;
        int above2 = (dsel < 127) ? s_scan[dsel + 1] : 0;
        krem -= above2;
        prefix21 |= ((unsigned)dsel) << shift;
        __syncthreads();
    }

    const unsigned kth_low = prefix21;

    for (int i = tid; i < ccnt; i += 256) {
        if (s_cu[i] > kth_low) {
            int p = atomicAdd(&s_cnt, 1);
            g_tv[r * K_TOP + p] = __uint_as_float(((unsigned)B1 << 21) | s_cu[i]);
            g_ti[r * K_TOP + p] = s_ci[i];
        }
    }
    __syncthreads();
    for (int i = tid; i < ccnt; i += 256) {
        if (s_cu[i] == kth_low) {
            int p = atomicAdd(&s_cnt, 1);
            if (p < K_TOP) {
                g_tv[r * K_TOP + p] = __uint_as_float(((unsigned)B1 << 21) | s_cu[i]);
                g_ti[r * K_TOP + p] = s_ci[i];
            }
        }
    }
}

// ---------------------------------------------------------------------------
// Sparse decode (unchanged)
// ---------------------------------------------------------------------------
__global__ __launch_bounds__(256)
void decode_kernel(const float* __restrict__ Wdec,
                   const float* __restrict__ b_dec,
                   float* __restrict__ out) {
    const int r = blockIdx.x;
    const int d = threadIdx.x;
    float acc = b_dec[d];
#pragma unroll
    for (int k = 0; k < K_TOP; k++) {
        float v  = g_tv[r * K_TOP + k];
        int   ix = g_ti[r * K_TOP + k];
        acc += v * __ldg(Wdec + (size_t)ix * D_SZ + d);
    }
    out[(size_t)r * D_SZ + d] = acc;
}

// ---------------------------------------------------------------------------
extern "C" void kernel_launch(void* const* d_in, const int* in_sizes, int n_in,
                              void* d_out, int out_size) {
    const float* x    = (const float*)d_in[0];
    const float* Wenc = (const float*)d_in[1];
    const float* benc = (const float*)d_in[2];
    const float* Wdec = (const float*)d_in[3];
    const float* bdec = (const float*)d_in[4];
    float* out = (float*)d_out;

    split_x_kernel<<<(B_SZ * D_SZ / 4) / 256, 256>>>(x, bdec);
    split_w_kernel<<<(H_SZ * D_SZ / 4) / 256, 256>>>(Wenc);

    static bool attr_set = false;
    if (!attr_set) {
        cudaFuncSetAttribute(enc_mma_kernel, cudaFuncAttributeMaxDynamicSharedMemorySize, SMEM_GEMM);
        attr_set = true;
    }
    dim3 grid(H_SZ / BN, B_SZ / BM);
    enc_mma_kernel<<<grid, 512, SMEM_GEMM>>>(benc);

    topk_kernel<<<B_SZ, 256>>>();

    decode_kernel<<<B_SZ, 256>>>(Wdec, bdec, out);
}

// round 6
// speedup vs baseline: 2.1476x; 1.0070x over previous
#include <cuda_runtime.h>
#include <cuda_fp16.h>
#include <cstdint>

#define B_SZ  8192
#define D_SZ  256
#define H_SZ  8192
#define K_TOP 32
#define KE    768             // 3 limb-chunks * 256 (fp16 2-limb, 3 cross terms)

// ---------------- scratch (static device globals) ----------------
__device__ float g_pre[(size_t)B_SZ * H_SZ];              // pre_acts (256 MB)
__device__ float g_tv[B_SZ * K_TOP];
__device__ int   g_ti[B_SZ * K_TOP];
__device__ __half g_A[(size_t)B_SZ * KE];                 // 12.6 MB
__device__ __half g_B[(size_t)H_SZ * KE];                 // 12.6 MB

// ---------------- helpers ----------------
__device__ __forceinline__ uint32_t smem_u32(const void* p) {
    uint32_t a;
    asm("{ .reg .u64 t; cvta.to.shared.u64 t, %1; cvt.u32.u64 %0, t; }" : "=r"(a) : "l"(p));
    return a;
}
__device__ __forceinline__ void cp_async16(uint32_t dst, const void* src) {
    asm volatile("cp.async.cg.shared.global [%0], [%1], 16;" :: "r"(dst), "l"(src));
}
#define CP_COMMIT() asm volatile("cp.async.commit_group;" ::: "memory")
#define CP_WAIT(n)  asm volatile("cp.async.wait_group %0;" :: "n"(n) : "memory")

__device__ __forceinline__ void ldsm4(uint32_t& r0, uint32_t& r1, uint32_t& r2, uint32_t& r3, uint32_t addr) {
    asm volatile("ldmatrix.sync.aligned.m8n8.x4.shared.b16 {%0,%1,%2,%3}, [%4];"
                 : "=r"(r0), "=r"(r1), "=r"(r2), "=r"(r3) : "r"(addr));
}
__device__ __forceinline__ void mma16816(float* d, const uint32_t* a, const uint32_t* b) {
    asm volatile("mma.sync.aligned.m16n8k16.row.col.f32.f16.f16.f32 "
                 "{%0,%1,%2,%3}, {%4,%5,%6,%7}, {%8,%9}, {%0,%1,%2,%3};"
                 : "+f"(d[0]), "+f"(d[1]), "+f"(d[2]), "+f"(d[3])
                 : "r"(a[0]), "r"(a[1]), "r"(a[2]), "r"(a[3]), "r"(b[0]), "r"(b[1]));
}

// ---------------------------------------------------------------------------
// Split kernels: 2-limb fp16 decomposition, interleaved along K'.
// A' = [a0 | a0 | a1],  B' = [b0 | b1 | b0]  -> terms a0b0 + a0b1 + a1b0.
// ---------------------------------------------------------------------------
__device__ __forceinline__ uint32_t packh2(__half lo, __half hi) {
    __half2 h = __halves2half2(lo, hi);
    return *reinterpret_cast<uint32_t*>(&h);
}

__global__ void split_x_kernel(const float* __restrict__ x, const float* __restrict__ b_dec) {
    int i = blockIdx.x * blockDim.x + threadIdx.x;     // float4 index
    int m = i >> 6;
    int kq = (i & 63) * 4;
    float4 xv = ((const float4*)x)[i];
    float4 bv = ((const float4*)b_dec)[i & 63];
    float v[4] = {xv.x - bv.x, xv.y - bv.y, xv.z - bv.z, xv.w - bv.w};
    __half h0[4], h1[4];
#pragma unroll
    for (int j = 0; j < 4; j++) {
        h0[j] = __float2half_rn(v[j]);
        h1[j] = __float2half_rn(v[j] - __half2float(h0[j]));
    }
    uint2 p0 = {packh2(h0[0], h0[1]), packh2(h0[2], h0[3])};
    uint2 p1 = {packh2(h1[0], h1[1]), packh2(h1[2], h1[3])};
    __half* row = g_A + (size_t)m * KE + kq;
    *(uint2*)(row + 0 * 256) = p0;       // a0
    *(uint2*)(row + 1 * 256) = p0;       // a0
    *(uint2*)(row + 2 * 256) = p1;       // a1
}

__global__ void split_w_kernel(const float* __restrict__ w) {
    int i = blockIdx.x * blockDim.x + threadIdx.x;
    int n = i >> 6;
    int kq = (i & 63) * 4;
    float4 wv = ((const float4*)w)[i];
    float v[4] = {wv.x, wv.y, wv.z, wv.w};
    __half h0[4], h1[4];
#pragma unroll
    for (int j = 0; j < 4; j++) {
        h0[j] = __float2half_rn(v[j]);
        h1[j] = __float2half_rn(v[j] - __half2float(h0[j]));
    }
    uint2 p0 = {packh2(h0[0], h0[1]), packh2(h0[2], h0[3])};
    uint2 p1 = {packh2(h1[0], h1[1]), packh2(h1[2], h1[3])};
    __half* row = g_B + (size_t)n * KE + kq;
    *(uint2*)(row + 0 * 256) = p0;       // b0
    *(uint2*)(row + 1 * 256) = p1;       // b1
    *(uint2*)(row + 2 * 256) = p0;       // b0
}

// ---------------------------------------------------------------------------
// Encoder GEMM: pre = relu(A' @ B'^T + b_enc), fp16 mma.sync, K=768.
// ---------------------------------------------------------------------------
#define BM 128
#define BN 256
#define GBK 32
#define STAGES 4
#define KT (KE / GBK)                       // 24
#define A_ST_BYTES (BM * GBK * 2)
#define B_ST_BYTES (BN * GBK * 2)
#define ST_BYTES   (A_ST_BYTES + B_ST_BYTES)
#define SMEM_GEMM  (STAGES * ST_BYTES)      // 98304

__device__ __forceinline__ uint32_t sw_off(int row, int c) {
    return (uint32_t)(row * 64 + ((c ^ ((row >> 1) & 3)) << 4));
}

__device__ __forceinline__ void stage_load(uint32_t sbase, int st, int kt, int tid,
                                           const __half* gA, const __half* gB) {
    uint32_t sa = sbase + st * ST_BYTES;
    uint32_t sb = sa + A_ST_BYTES;
    int k0 = kt * GBK;
    {
        int row = tid >> 2, c = tid & 3;
        cp_async16(sa + sw_off(row, c), gA + (size_t)row * KE + k0 + c * 8);
    }
#pragma unroll
    for (int i = 0; i < 2; i++) {
        int idx = tid + i * 512;
        int row = idx >> 2, c = idx & 3;
        cp_async16(sb + sw_off(row, c), gB + (size_t)row * KE + k0 + c * 8);
    }
}

__global__ __launch_bounds__(512, 1)
void enc_mma_kernel(const float* __restrict__ b_enc) {
    extern __shared__ char smem[];
    __shared__ float s_be[BN];

    const uint32_t sbase = smem_u32(smem);
    const int tid = threadIdx.x;
    const int wid = tid >> 5, lid = tid & 31;
    const int n0 = blockIdx.x * BN;
    const int m0 = blockIdx.y * BM;
    const int wm = (wid & 3) * 32;
    const int wn = (wid >> 2) * 64;

    if (tid < BN) s_be[tid] = b_enc[n0 + tid];

    const __half* gA = g_A + (size_t)m0 * KE;
    const __half* gB = g_B + (size_t)n0 * KE;

    float d[2][8][4];
#pragma unroll
    for (int mt = 0; mt < 2; mt++)
#pragma unroll
        for (int nt = 0; nt < 8; nt++)
#pragma unroll
            for (int j = 0; j < 4; j++) d[mt][nt][j] = 0.0f;

#pragma unroll
    for (int s = 0; s < STAGES - 1; s++) { stage_load(sbase, s, s, tid, gA, gB); CP_COMMIT(); }

    const int g  = lid >> 3;
    const int lr = lid & 7;

#pragma unroll 1
    for (int kt = 0; kt < KT; kt++) {
        CP_WAIT(2);
        __syncthreads();
        const int st = kt & (STAGES - 1);
        const uint32_t sa = sbase + st * ST_BYTES;
        const uint32_t sb = sa + A_ST_BYTES;

        if (kt + STAGES - 1 < KT)
            stage_load(sbase, (kt + STAGES - 1) & (STAGES - 1), kt + STAGES - 1, tid, gA, gB);
        CP_COMMIT();

#pragma unroll
        for (int ks = 0; ks < 2; ks++) {
            uint32_t a[2][4], b[4][4];
#pragma unroll
            for (int mt = 0; mt < 2; mt++) {
                int row = wm + mt * 16 + (g & 1) * 8 + lr;
                int c   = ks * 2 + (g >> 1);
                ldsm4(a[mt][0], a[mt][1], a[mt][2], a[mt][3], sa + sw_off(row, c));
            }
#pragma unroll
            for (int np = 0; np < 4; np++) {
                int row = wn + (np * 2 + (g >> 1)) * 8 + lr;
                int c   = ks * 2 + (g & 1);
                ldsm4(b[np][0], b[np][1], b[np][2], b[np][3], sb + sw_off(row, c));
            }
#pragma unroll
            for (int mt = 0; mt < 2; mt++)
#pragma unroll
                for (int nt = 0; nt < 8; nt++)
                    mma16816(d[mt][nt], a[mt], &b[nt >> 1][(nt & 1) * 2]);
        }
        __syncthreads();
    }

#pragma unroll
    for (int mt = 0; mt < 2; mt++) {
        int row0 = m0 + wm + mt * 16 + (lid >> 2);
#pragma unroll
        for (int nt = 0; nt < 8; nt++) {
            int coll = wn + nt * 8 + (lid & 3) * 2;
            float be0 = s_be[coll], be1 = s_be[coll + 1];
            float2 o0, o1;
            o0.x = fmaxf(d[mt][nt][0] + be0, 0.0f);
            o0.y = fmaxf(d[mt][nt][1] + be1, 0.0f);
            o1.x = fmaxf(d[mt][nt][2] + be0, 0.0f);
            o1.y = fmaxf(d[mt][nt][3] + be1, 0.0f);
            *(float2*)(g_pre + (size_t)row0 * H_SZ + n0 + coll)       = o0;
            *(float2*)(g_pre + (size_t)(row0 + 8) * H_SZ + n0 + coll) = o1;
        }
    }
}

// ---------------------------------------------------------------------------
// Top-32: streaming histogram pass (no register row cache), then L2-hit
// re-read for classification; candidates refined by 3x7-bit radix. Exact.
// ---------------------------------------------------------------------------
#define HBINS 2048
#define CAP   2048

__global__ __launch_bounds__(256)
void topk_kernel() {
    __shared__ int s_hist[HBINS];
    __shared__ int s_scan[256];
    __shared__ unsigned s_cu[CAP];
    __shared__ int s_ci[CAP];
    __shared__ int s_B1, s_above, s_cnt, s_ccnt, s_sel;

    const int tid = threadIdx.x;
    const int r = blockIdx.x;
    const float4* row4 = (const float4*)(g_pre + (size_t)r * H_SZ);

    if (tid < K_TOP) { g_tv[r * K_TOP + tid] = 0.0f; g_ti[r * K_TOP + tid] = 0; }
#pragma unroll
    for (int i = tid; i < HBINS; i += 256) s_hist[i] = 0;
    if (tid == 0) { s_B1 = -1; s_above = 0; s_cnt = 0; s_ccnt = 0; }
    __syncthreads();

    // Pass 1: streaming histogram (11-bit key = exponent + 3 mantissa bits)
#pragma unroll
    for (int j = 0; j < 8; j++) {
        float4 v = row4[tid + j * 256];
        unsigned a0 = __float_as_uint(v.x), a1 = __float_as_uint(v.y);
        unsigned a2 = __float_as_uint(v.z), a3 = __float_as_uint(v.w);
        if (a0) atomicAdd(&s_hist[a0 >> 21], 1);
        if (a1) atomicAdd(&s_hist[a1 >> 21], 1);
        if (a2) atomicAdd(&s_hist[a2 >> 21], 1);
        if (a3) atomicAdd(&s_hist[a3 >> 21], 1);
    }
    __syncthreads();

    // Suffix scan over 2048 bins (thread t owns bins [t*8, t*8+8))
    int local = 0;
#pragma unroll
    for (int b = 0; b < 8; b++) local += s_hist[tid * 8 + b];
    s_scan[tid] = local;
    __syncthreads();
#pragma unroll 1
    for (int off = 1; off < 256; off <<= 1) {
        int add = (tid + off < 256) ? s_scan[tid + off] : 0;
        __syncthreads();
        s_scan[tid] += add;
        __syncthreads();
    }
    const int total = s_scan[0];
    {
        int run = s_scan[tid] - local;
#pragma unroll
        for (int b = 7; b >= 0; b--) {
            int h = s_hist[tid * 8 + b];
            if (run < K_TOP && run + h >= K_TOP) { s_B1 = tid * 8 + b; s_above = run; }
            run += h;
        }
    }
    __syncthreads();

    if (total < K_TOP) {
        // fewer than 32 nonzero: take all (row is L2-resident on re-read)
#pragma unroll
        for (int j = 0; j < 8; j++) {
            float4 v = row4[tid + j * 256];
            unsigned a[4] = {__float_as_uint(v.x), __float_as_uint(v.y),
                             __float_as_uint(v.z), __float_as_uint(v.w)};
#pragma unroll
            for (int c = 0; c < 4; c++) {
                if (a[c]) {
                    int p = atomicAdd(&s_cnt, 1);
                    g_tv[r * K_TOP + p] = __uint_as_float(a[c]);
                    g_ti[r * K_TOP + p] = (tid + j * 256) * 4 + c;
                }
            }
        }
        return;
    }

    const int B1 = s_B1;

    // Pass 2: re-read (L2 hit); winners direct, bucket ties to candidate list
#pragma unroll
    for (int j = 0; j < 8; j++) {
        float4 v = row4[tid + j * 256];
        unsigned a[4] = {__float_as_uint(v.x), __float_as_uint(v.y),
                         __float_as_uint(v.z), __float_as_uint(v.w)};
#pragma unroll
        for (int c = 0; c < 4; c++) {
            unsigned uu = a[c];
            if (!uu) continue;
            int key = (int)(uu >> 21);
            int idx = (tid + j * 256) * 4 + c;
            if (key > B1) {
                int p = atomicAdd(&s_cnt, 1);
                g_tv[r * K_TOP + p] = __uint_as_float(uu);
                g_ti[r * K_TOP + p] = idx;
            } else if (key == B1) {
                int p = atomicAdd(&s_ccnt, 1);
                if (p < CAP) { s_cu[p] = uu & 0x1FFFFFu; s_ci[p] = idx; }
            }
        }
    }
    __syncthreads();

    const int above = s_above;
    int krem = K_TOP - above;
    int ccnt = s_ccnt < CAP ? s_ccnt : CAP;

    if (ccnt <= krem) {
        for (int i = tid; i < ccnt; i += 256) {
            int p = atomicAdd(&s_cnt, 1);
            g_tv[r * K_TOP + p] = __uint_as_float(((unsigned)B1 << 21) | s_cu[i]);
            g_ti[r * K_TOP + p] = s_ci[i];
        }
        return;
    }

    // Refine: exact select of top-krem among candidates (3x7-bit radix)
    unsigned prefix21 = 0;
#pragma unroll 1
    for (int shift = 14; shift >= 0; shift -= 7) {
        if (tid < 128) s_hist[tid] = 0;
        if (tid == 0) s_sel = 0;
        __syncthreads();
        unsigned pmask = (shift == 14) ? 0u : ((0x1FFFFFu << (shift + 7)) & 0x1FFFFFu);
        for (int i = tid; i < ccnt; i += 256) {
            unsigned cu = s_cu[i];
            if ((cu & pmask) == prefix21) atomicAdd(&s_hist[(cu >> shift) & 127], 1);
        }
        __syncthreads();
        if (tid < 128) s_scan[tid] = s_hist[tid];
        __syncthreads();
#pragma unroll 1
        for (int off = 1; off < 128; off <<= 1) {
            int add = (tid < 128 && tid + off < 128) ? s_scan[tid + off] : 0;
            __syncthreads();
            if (tid < 128) s_scan[tid] += add;
            __syncthreads();
        }
        if (tid < 128) {
            int nxt = (tid < 127) ? s_scan[tid + 1] : 0;
            if (s_scan[tid] >= krem && nxt < krem) s_sel = tid;
        }
        __syncthreads();
        int dsel = s_sel;
        int above2 = (dsel < 127) ? s_scan[dsel + 1] : 0;
        krem -= above2;
        prefix21 |= ((unsigned)dsel) << shift;
        __syncthreads();
    }

    const unsigned kth_low = prefix21;

    for (int i = tid; i < ccnt; i += 256) {
        if (s_cu[i] > kth_low) {
            int p = atomicAdd(&s_cnt, 1);
            g_tv[r * K_TOP + p] = __uint_as_float(((unsigned)B1 << 21) | s_cu[i]);
            g_ti[r * K_TOP + p] = s_ci[i];
        }
    }
    __syncthreads();
    for (int i = tid; i < ccnt; i += 256) {
        if (s_cu[i] == kth_low) {
            int p = atomicAdd(&s_cnt, 1);
            if (p < K_TOP) {
                g_tv[r * K_TOP + p] = __uint_as_float(((unsigned)B1 << 21) | s_cu[i]);
                g_ti[r * K_TOP + p] = s_ci[i];
            }
        }
    }
}

// ---------------------------------------------------------------------------
// Sparse decode (unchanged)
// ---------------------------------------------------------------------------
__global__ __launch_bounds__(256)
void decode_kernel(const float* __restrict__ Wdec,
                   const float* __restrict__ b_dec,
                   float* __restrict__ out) {
    const int r = blockIdx.x;
    const int d = threadIdx.x;
    float acc = b_dec[d];
#pragma unroll
    for (int k = 0; k < K_TOP; k++) {
        float v  = g_tv[r * K_TOP + k];
        int   ix = g_ti[r * K_TOP + k];
        acc += v * __ldg(Wdec + (size_t)ix * D_SZ + d);
    }
    out[(size_t)r * D_SZ + d] = acc;
}

// ---------------------------------------------------------------------------
extern "C" void kernel_launch(void* const* d_in, const int* in_sizes, int n_in,
                              void* d_out, int out_size) {
    const float* x    = (const float*)d_in[0];
    const float* Wenc = (const float*)d_in[1];
    const float* benc = (const float*)d_in[2];
    const float* Wdec = (const float*)d_in[3];
    const float* bdec = (const float*)d_in[4];
    float* out = (float*)d_out;

    split_x_kernel<<<(B_SZ * D_SZ / 4) / 256, 256>>>(x, bdec);
    split_w_kernel<<<(H_SZ * D_SZ / 4) / 256, 256>>>(Wenc);

    static bool attr_set = false;
    if (!attr_set) {
        cudaFuncSetAttribute(enc_mma_kernel, cudaFuncAttributeMaxDynamicSharedMemorySize, SMEM_GEMM);
        attr_set = true;
    }
    dim3 grid(H_SZ / BN, B_SZ / BM);
    enc_mma_kernel<<<grid, 512, SMEM_GEMM>>>(benc);

    topk_kernel<<<B_SZ, 256>>>();

    decode_kernel<<<B_SZ, 256>>>(Wdec, bdec, out);
}

// round 8
// speedup vs baseline: 2.1820x; 1.0160x over previous
#include <cuda_runtime.h>
#include <cuda_fp16.h>
#include <cstdint>

#define B_SZ  8192
#define D_SZ  256
#define H_SZ  8192
#define K_TOP 32
#define KE    768             // 3 limb-chunks * 256 (fp16 2-limb, 3 cross terms)

// ---------------- scratch (static device globals) ----------------
__device__ float g_pre[(size_t)B_SZ * H_SZ];              // pre_acts (256 MB)
__device__ float g_tv[B_SZ * K_TOP];
__device__ int   g_ti[B_SZ * K_TOP];
__device__ __half g_A[(size_t)B_SZ * KE];                 // 12.6 MB
__device__ __half g_B[(size_t)H_SZ * KE];                 // 12.6 MB

// ---------------- helpers ----------------
__device__ __forceinline__ uint32_t smem_u32(const void* p) {
    uint32_t a;
    asm("{ .reg .u64 t; cvta.to.shared.u64 t, %1; cvt.u32.u64 %0, t; }" : "=r"(a) : "l"(p));
    return a;
}
__device__ __forceinline__ void cp_async16(uint32_t dst, const void* src) {
    asm volatile("cp.async.cg.shared.global [%0], [%1], 16;" :: "r"(dst), "l"(src));
}
#define CP_COMMIT() asm volatile("cp.async.commit_group;" ::: "memory")
#define CP_WAIT(n)  asm volatile("cp.async.wait_group %0;" :: "n"(n) : "memory")

__device__ __forceinline__ void ldsm4(uint32_t& r0, uint32_t& r1, uint32_t& r2, uint32_t& r3, uint32_t addr) {
    asm volatile("ldmatrix.sync.aligned.m8n8.x4.shared.b16 {%0,%1,%2,%3}, [%4];"
                 : "=r"(r0), "=r"(r1), "=r"(r2), "=r"(r3) : "r"(addr));
}
__device__ __forceinline__ void mma16816(float* d, const uint32_t* a, const uint32_t* b) {
    asm volatile("mma.sync.aligned.m16n8k16.row.col.f32.f16.f16.f32 "
                 "{%0,%1,%2,%3}, {%4,%5,%6,%7}, {%8,%9}, {%0,%1,%2,%3};"
                 : "+f"(d[0]), "+f"(d[1]), "+f"(d[2]), "+f"(d[3])
                 : "r"(a[0]), "r"(a[1]), "r"(a[2]), "r"(a[3]), "r"(b[0]), "r"(b[1]));
}

// ---------------------------------------------------------------------------
// Split kernels: 2-limb fp16 decomposition, interleaved along K'.
// A' = [a0 | a0 | a1],  B' = [b0 | b1 | b0]  -> terms a0b0 + a0b1 + a1b0.
// ---------------------------------------------------------------------------
__device__ __forceinline__ uint32_t packh2(__half lo, __half hi) {
    __half2 h = __halves2half2(lo, hi);
    return *reinterpret_cast<uint32_t*>(&h);
}

__global__ void split_x_kernel(const float* __restrict__ x, const float* __restrict__ b_dec) {
    int i = blockIdx.x * blockDim.x + threadIdx.x;     // float4 index
    int m = i >> 6;
    int kq = (i & 63) * 4;
    float4 xv = ((const float4*)x)[i];
    float4 bv = ((const float4*)b_dec)[i & 63];
    float v[4] = {xv.x - bv.x, xv.y - bv.y, xv.z - bv.z, xv.w - bv.w};
    __half h0[4], h1[4];
#pragma unroll
    for (int j = 0; j < 4; j++) {
        h0[j] = __float2half_rn(v[j]);
        h1[j] = __float2half_rn(v[j] - __half2float(h0[j]));
    }
    uint2 p0 = {packh2(h0[0], h0[1]), packh2(h0[2], h0[3])};
    uint2 p1 = {packh2(h1[0], h1[1]), packh2(h1[2], h1[3])};
    __half* row = g_A + (size_t)m * KE + kq;
    *(uint2*)(row + 0 * 256) = p0;       // a0
    *(uint2*)(row + 1 * 256) = p0;       // a0
    *(uint2*)(row + 2 * 256) = p1;       // a1
}

__global__ void split_w_kernel(const float* __restrict__ w) {
    int i = blockIdx.x * blockDim.x + threadIdx.x;
    int n = i >> 6;
    int kq = (i & 63) * 4;
    float4 wv = ((const float4*)w)[i];
    float v[4] = {wv.x, wv.y, wv.z, wv.w};
    __half h0[4], h1[4];
#pragma unroll
    for (int j = 0; j < 4; j++) {
        h0[j] = __float2half_rn(v[j]);
        h1[j] = __float2half_rn(v[j] - __half2float(h0[j]));
    }
    uint2 p0 = {packh2(h0[0], h0[1]), packh2(h0[2], h0[3])};
    uint2 p1 = {packh2(h1[0], h1[1]), packh2(h1[2], h1[3])};
    __half* row = g_B + (size_t)n * KE + kq;
    *(uint2*)(row + 0 * 256) = p0;       // b0
    *(uint2*)(row + 1 * 256) = p1;       // b1
    *(uint2*)(row + 2 * 256) = p0;       // b0
}

// ---------------------------------------------------------------------------
// Encoder GEMM: pre = relu(A' @ B'^T + b_enc), fp16 mma.sync, K=768. (R5/R6)
// ---------------------------------------------------------------------------
#define BM 128
#define BN 256
#define GBK 32
#define STAGES 4
#define KT (KE / GBK)                       // 24
#define A_ST_BYTES (BM * GBK * 2)
#define B_ST_BYTES (BN * GBK * 2)
#define ST_BYTES   (A_ST_BYTES + B_ST_BYTES)
#define SMEM_GEMM  (STAGES * ST_BYTES)      // 98304

__device__ __forceinline__ uint32_t sw_off(int row, int c) {
    return (uint32_t)(row * 64 + ((c ^ ((row >> 1) & 3)) << 4));
}

__device__ __forceinline__ void stage_load(uint32_t sbase, int st, int kt, int tid,
                                           const __half* gA, const __half* gB) {
    uint32_t sa = sbase + st * ST_BYTES;
    uint32_t sb = sa + A_ST_BYTES;
    int k0 = kt * GBK;
    {
        int row = tid >> 2, c = tid & 3;
        cp_async16(sa + sw_off(row, c), gA + (size_t)row * KE + k0 + c * 8);
    }
#pragma unroll
    for (int i = 0; i < 2; i++) {
        int idx = tid + i * 512;
        int row = idx >> 2, c = idx & 3;
        cp_async16(sb + sw_off(row, c), gB + (size_t)row * KE + k0 + c * 8);
    }
}

__global__ __launch_bounds__(512, 1)
void enc_mma_kernel(const float* __restrict__ b_enc) {
    extern __shared__ char smem[];
    __shared__ float s_be[BN];

    const uint32_t sbase = smem_u32(smem);
    const int tid = threadIdx.x;
    const int wid = tid >> 5, lid = tid & 31;
    const int n0 = blockIdx.x * BN;
    const int m0 = blockIdx.y * BM;
    const int wm = (wid & 3) * 32;
    const int wn = (wid >> 2) * 64;

    if (tid < BN) s_be[tid] = b_enc[n0 + tid];

    const __half* gA = g_A + (size_t)m0 * KE;
    const __half* gB = g_B + (size_t)n0 * KE;

    float d[2][8][4];
#pragma unroll
    for (int mt = 0; mt < 2; mt++)
#pragma unroll
        for (int nt = 0; nt < 8; nt++)
#pragma unroll
            for (int j = 0; j < 4; j++) d[mt][nt][j] = 0.0f;

#pragma unroll
    for (int s = 0; s < STAGES - 1; s++) { stage_load(sbase, s, s, tid, gA, gB); CP_COMMIT(); }

    const int g  = lid >> 3;
    const int lr = lid & 7;

#pragma unroll 1
    for (int kt = 0; kt < KT; kt++) {
        CP_WAIT(2);
        __syncthreads();
        const int st = kt & (STAGES - 1);
        const uint32_t sa = sbase + st * ST_BYTES;
        const uint32_t sb = sa + A_ST_BYTES;

        if (kt + STAGES - 1 < KT)
            stage_load(sbase, (kt + STAGES - 1) & (STAGES - 1), kt + STAGES - 1, tid, gA, gB);
        CP_COMMIT();

#pragma unroll
        for (int ks = 0; ks < 2; ks++) {
            uint32_t a[2][4], b[4][4];
#pragma unroll
            for (int mt = 0; mt < 2; mt++) {
                int row = wm + mt * 16 + (g & 1) * 8 + lr;
                int c   = ks * 2 + (g >> 1);
                ldsm4(a[mt][0], a[mt][1], a[mt][2], a[mt][3], sa + sw_off(row, c));
            }
#pragma unroll
            for (int np = 0; np < 4; np++) {
                int row = wn + (np * 2 + (g >> 1)) * 8 + lr;
                int c   = ks * 2 + (g & 1);
                ldsm4(b[np][0], b[np][1], b[np][2], b[np][3], sb + sw_off(row, c));
            }
#pragma unroll
            for (int mt = 0; mt < 2; mt++)
#pragma unroll
                for (int nt = 0; nt < 8; nt++)
                    mma16816(d[mt][nt], a[mt], &b[nt >> 1][(nt & 1) * 2]);
        }
        __syncthreads();
    }

#pragma unroll
    for (int mt = 0; mt < 2; mt++) {
        int row0 = m0 + wm + mt * 16 + (lid >> 2);
#pragma unroll
        for (int nt = 0; nt < 8; nt++) {
            int coll = wn + nt * 8 + (lid & 3) * 2;
            float be0 = s_be[coll], be1 = s_be[coll + 1];
            float2 o0, o1;
            o0.x = fmaxf(d[mt][nt][0] + be0, 0.0f);
            o0.y = fmaxf(d[mt][nt][1] + be1, 0.0f);
            o1.x = fmaxf(d[mt][nt][2] + be0, 0.0f);
            o1.y = fmaxf(d[mt][nt][3] + be1, 0.0f);
            *(float2*)(g_pre + (size_t)row0 * H_SZ + n0 + coll)       = o0;
            *(float2*)(g_pre + (size_t)(row0 + 8) * H_SZ + n0 + coll) = o1;
        }
    }
}

// ---------------------------------------------------------------------------
// Top-32 v3: threshold prefilter (v > 2.0) -> small survivor list -> exact
// select on list. Fallback to full-row histogram path if list underflows or
// overflows. Hierarchical warp scans (1 barrier instead of 16).
// ---------------------------------------------------------------------------
#define HBINS   2048
#define CAP     2048     // candidate list (fallback ties)
#define SCAP    1024     // survivor list
#define T_BITS  0x40000000u   // 2.0f

// inclusive suffix sums over 2048 bins with 256 threads: thread t owns bins
// [t*8, t*8+8). Returns per-thread local sum and inclusive suffix (incl own).
__device__ __forceinline__ void suffix2048(const int* s_hist, int* s_warp, int tid,
                                           int& local, int& suf_incl, int& total) {
    local = 0;
#pragma unroll
    for (int b = 0; b < 8; b++) local += s_hist[tid * 8 + b];
    int v = local;
    const int lane = tid & 31, w = tid >> 5;
#pragma unroll
    for (int off = 1; off < 32; off <<= 1) {
        int t = __shfl_down_sync(0xFFFFFFFFu, v, off);
        if (lane + off < 32) v += t;
    }
    if (lane == 0) s_warp[w] = v;       // warp total
    __syncthreads();
    int add = 0;
#pragma unroll
    for (int ww = 0; ww < 8; ww++) if (ww > w) add += s_warp[ww];
    suf_incl = v + add;
    total = 0;
#pragma unroll
    for (int ww = 0; ww < 8; ww++) total += s_warp[ww];
}

__global__ __launch_bounds__(256)
void topk_kernel() {
    __shared__ int s_hist[HBINS];
    __shared__ int s_warp[8];
    __shared__ int s_scan[128];
    __shared__ unsigned s_su[SCAP];
    __shared__ int s_si[SCAP];
    __shared__ unsigned s_cu[CAP];
    __shared__ int s_ci[CAP];
    __shared__ int s_B1, s_above, s_cnt, s_ccnt, s_scnt, s_sel;

    const int tid = threadIdx.x;
    const int r = blockIdx.x;
    const float4* row4 = (const float4*)(g_pre + (size_t)r * H_SZ);

    if (tid < K_TOP) { g_tv[r * K_TOP + tid] = 0.0f; g_ti[r * K_TOP + tid] = 0; }
#pragma unroll
    for (int i = tid; i < HBINS; i += 256) s_hist[i] = 0;
    if (tid == 0) { s_B1 = -1; s_above = 0; s_cnt = 0; s_ccnt = 0; s_scnt = 0; }
    __syncthreads();

    // Pass 1: stream row, collect survivors (> 2.0)
#pragma unroll
    for (int j = 0; j < 8; j++) {
        float4 v = row4[tid + j * 256];
        unsigned a[4] = {__float_as_uint(v.x), __float_as_uint(v.y),
                         __float_as_uint(v.z), __float_as_uint(v.w)};
#pragma unroll
        for (int c = 0; c < 4; c++) {
            if (a[c] > T_BITS) {
                int p = atomicAdd(&s_scnt, 1);
                if (p < SCAP) { s_su[p] = a[c]; s_si[p] = (tid + j * 256) * 4 + c; }
            }
        }
    }
    __syncthreads();
    const int scnt = s_scnt;

    if (scnt >= K_TOP && scnt <= SCAP) {
        // ---------------- fast path: exact select among survivors ----------------
        for (int i = tid; i < scnt; i += 256) atomicAdd(&s_hist[s_su[i] >> 21], 1);
        __syncthreads();

        int local, suf, total;
        suffix2048(s_hist, s_warp, tid, local, suf, total);
        {
            int run = suf - local;
#pragma unroll
            for (int b = 7; b >= 0; b--) {
                int h = s_hist[tid * 8 + b];
                if (run < K_TOP && run + h >= K_TOP) { s_B1 = tid * 8 + b; s_above = run; }
                run += h;
            }
        }
        __syncthreads();
        const int B1 = s_B1;

        for (int i = tid; i < scnt; i += 256) {
            unsigned uu = s_su[i];
            int key = (int)(uu >> 21);
            if (key > B1) {
                int p = atomicAdd(&s_cnt, 1);
                g_tv[r * K_TOP + p] = __uint_as_float(uu);
                g_ti[r * K_TOP + p] = s_si[i];
            } else if (key == B1) {
                int p = atomicAdd(&s_ccnt, 1);
                s_cu[p] = uu & 0x1FFFFFu; s_ci[p] = s_si[i];
            }
        }
        __syncthreads();

        int krem = K_TOP - s_above;
        int ccnt = s_ccnt;

        if (ccnt <= krem) {
            for (int i = tid; i < ccnt; i += 256) {
                int p = atomicAdd(&s_cnt, 1);
                g_tv[r * K_TOP + p] = __uint_as_float(((unsigned)B1 << 21) | s_cu[i]);
                g_ti[r * K_TOP + p] = s_ci[i];
            }
            return;
        }

        // refine: 3x7-bit radix over 21-bit suffixes of candidates
        unsigned prefix21 = 0;
#pragma unroll 1
        for (int shift = 14; shift >= 0; shift -= 7) {
            if (tid < 128) s_hist[tid] = 0;
            if (tid == 0) s_sel = 0;
            __syncthreads();
            unsigned pmask = (shift == 14) ? 0u : ((0x1FFFFFu << (shift + 7)) & 0x1FFFFFu);
            for (int i = tid; i < ccnt; i += 256) {
                unsigned cu = s_cu[i];
                if ((cu & pmask) == prefix21) atomicAdd(&s_hist[(cu >> shift) & 127], 1);
            }
            __syncthreads();
            if (tid < 128) s_scan[tid] = s_hist[tid];
            __syncthreads();
#pragma unroll 1
            for (int off = 1; off < 128; off <<= 1) {
                int add = (tid < 128 && tid + off < 128) ? s_scan[tid + off] : 0;
                __syncthreads();
                if (tid < 128) s_scan[tid] += add;
                __syncthreads();
            }
            if (tid < 128) {
                int nxt = (tid < 127) ? s_scan[tid + 1] : 0;
                if (s_scan[tid] >= krem && nxt < krem) s_sel = tid;
            }
            __syncthreads();
            int dsel = s_sel;
            int above2 = (dsel < 127) ? s_scan[dsel + 1] : 0;
            krem -= above2;
            prefix21 |= ((unsigned)dsel) << shift;
            __syncthreads();
        }
        const unsigned kth_low = prefix21;
        for (int i = tid; i < ccnt; i += 256) {
            if (s_cu[i] > kth_low) {
                int p = atomicAdd(&s_cnt, 1);
                g_tv[r * K_TOP + p] = __uint_as_float(((unsigned)B1 << 21) | s_cu[i]);
                g_ti[r * K_TOP + p] = s_ci[i];
            }
        }
        __syncthreads();
        for (int i = tid; i < ccnt; i += 256) {
            if (s_cu[i] == kth_low) {
                int p = atomicAdd(&s_cnt, 1);
                if (p < K_TOP) {
                    g_tv[r * K_TOP + p] = __uint_as_float(((unsigned)B1 << 21) | s_cu[i]);
                    g_ti[r * K_TOP + p] = s_ci[i];
                }
            }
        }
        return;
    }

    // ---------------- fallback: full-row histogram path (exact, R6) ----------------
#pragma unroll
    for (int j = 0; j < 8; j++) {
        float4 v = row4[tid + j * 256];
        unsigned a0 = __float_as_uint(v.x), a1 = __float_as_uint(v.y);
        unsigned a2 = __float_as_uint(v.z), a3 = __float_as_uint(v.w);
        if (a0) atomicAdd(&s_hist[a0 >> 21], 1);
        if (a1) atomicAdd(&s_hist[a1 >> 21], 1);
        if (a2) atomicAdd(&s_hist[a2 >> 21], 1);
        if (a3) atomicAdd(&s_hist[a3 >> 21], 1);
    }
    __syncthreads();

    int local, suf, total;
    suffix2048(s_hist, s_warp, tid, local, suf, total);
    {
        int run = suf - local;
#pragma unroll
        for (int b = 7; b >= 0; b--) {
            int h = s_hist[tid * 8 + b];
            if (run < K_TOP && run + h >= K_TOP) { s_B1 = tid * 8 + b; s_above = run; }
            run += h;
        }
    }
    __syncthreads();

    if (total < K_TOP) {
#pragma unroll
        for (int j = 0; j < 8; j++) {
            float4 v = row4[tid + j * 256];
            unsigned a[4] = {__float_as_uint(v.x), __float_as_uint(v.y),
                             __float_as_uint(v.z), __float_as_uint(v.w)};
#pragma unroll
            for (int c = 0; c < 4; c++) {
                if (a[c]) {
                    int p = atomicAdd(&s_cnt, 1);
                    g_tv[r * K_TOP + p] = __uint_as_float(a[c]);
                    g_ti[r * K_TOP + p] = (tid + j * 256) * 4 + c;
                }
            }
        }
        return;
    }

    const int B1 = s_B1;
#pragma unroll
    for (int j = 0; j < 8; j++) {
        float4 v = row4[tid + j * 256];
        unsigned a[4] = {__float_as_uint(v.x), __float_as_uint(v.y),
                         __float_as_uint(v.z), __float_as_uint(v.w)};
#pragma unroll
        for (int c = 0; c < 4; c++) {
            unsigned uu = a[c];
            if (!uu) continue;
            int key = (int)(uu >> 21);
            int idx = (tid + j * 256) * 4 + c;
            if (key > B1) {
                int p = atomicAdd(&s_cnt, 1);
                g_tv[r * K_TOP + p] = __uint_as_float(uu);
                g_ti[r * K_TOP + p] = idx;
            } else if (key == B1) {
                int p = atomicAdd(&s_ccnt, 1);
                if (p < CAP) { s_cu[p] = uu & 0x1FFFFFu; s_ci[p] = idx; }
            }
        }
    }
    __syncthreads();

    int krem = K_TOP - s_above;
    int ccnt = s_ccnt < CAP ? s_ccnt : CAP;

    if (ccnt <= krem) {
        for (int i = tid; i < ccnt; i += 256) {
            int p = atomicAdd(&s_cnt, 1);
            g_tv[r * K_TOP + p] = __uint_as_float(((unsigned)B1 << 21) | s_cu[i]);
            g_ti[r * K_TOP + p] = s_ci[i];
        }
        return;
    }

    unsigned prefix21 = 0;
#pragma unroll 1
    for (int shift = 14; shift >= 0; shift -= 7) {
        if (tid < 128) s_hist[tid] = 0;
        if (tid == 0) s_sel = 0;
        __syncthreads();
        unsigned pmask = (shift == 14) ? 0u : ((0x1FFFFFu << (shift + 7)) & 0x1FFFFFu);
        for (int i = tid; i < ccnt; i += 256) {
            unsigned cu = s_cu[i];
            if ((cu & pmask) == prefix21) atomicAdd(&s_hist[(cu >> shift) & 127], 1);
        }
        __syncthreads();
        if (tid < 128) s_scan[tid] = s_hist[tid];
        __syncthreads();
#pragma unroll 1
        for (int off = 1; off < 128; off <<= 1) {
            int add = (tid < 128 && tid + off < 128) ? s_scan[tid + off] : 0;
            __syncthreads();
            if (tid < 128) s_scan[tid] += add;
            __syncthreads();
        }
        if (tid < 128) {
            int nxt = (tid < 127) ? s_scan[tid + 1] : 0;
            if (s_scan[tid] >= krem && nxt < krem) s_sel = tid;
        }
        __syncthreads();
        int dsel = s_sel;
        int above2 = (dsel < 127) ? s_scan[dsel + 1] : 0;
        krem -= above2;
        prefix21 |= ((unsigned)dsel) << shift;
        __syncthreads();
    }
    const unsigned kth_low = prefix21;

    for (int i = tid; i < ccnt; i += 256) {
        if (s_cu[i] > kth_low) {
            int p = atomicAdd(&s_cnt, 1);
            g_tv[r * K_TOP + p] = __uint_as_float(((unsigned)B1 << 21) | s_cu[i]);
            g_ti[r * K_TOP + p] = s_ci[i];
        }
    }
    __syncthreads();
    for (int i = tid; i < ccnt; i += 256) {
        if (s_cu[i] == kth_low) {
            int p = atomicAdd(&s_cnt, 1);
            if (p < K_TOP) {
                g_tv[r * K_TOP + p] = __uint_as_float(((unsigned)B1 << 21) | s_cu[i]);
                g_ti[r * K_TOP + p] = s_ci[i];
            }
        }
    }
}

// ---------------------------------------------------------------------------
// Sparse decode (unchanged)
// ---------------------------------------------------------------------------
__global__ __launch_bounds__(256)
void decode_kernel(const float* __restrict__ Wdec,
                   const float* __restrict__ b_dec,
                   float* __restrict__ out) {
    const int r = blockIdx.x;
    const int d = threadIdx.x;
    float acc = b_dec[d];
#pragma unroll
    for (int k = 0; k < K_TOP; k++) {
        float v  = g_tv[r * K_TOP + k];
        int   ix = g_ti[r * K_TOP + k];
        acc += v * __ldg(Wdec + (size_t)ix * D_SZ + d);
    }
    out[(size_t)r * D_SZ + d] = acc;
}

// ---------------------------------------------------------------------------
extern "C" void kernel_launch(void* const* d_in, const int* in_sizes, int n_in,
                              void* d_out, int out_size) {
    const float* x    = (const float*)d_in[0];
    const float* Wenc = (const float*)d_in[1];
    const float* benc = (const float*)d_in[2];
    const float* Wdec = (const float*)d_in[3];
    const float* bdec = (const float*)d_in[4];
    float* out = (float*)d_out;

    split_x_kernel<<<(B_SZ * D_SZ / 4) / 256, 256>>>(x, bdec);
    split_w_kernel<<<(H_SZ * D_SZ / 4) / 256, 256>>>(Wenc);

    static bool attr_set = false;
    if (!attr_set) {
        cudaFuncSetAttribute(enc_mma_kernel, cudaFuncAttributeMaxDynamicSharedMemorySize, SMEM_GEMM);
        attr_set = true;
    }
    dim3 grid(H_SZ / BN, B_SZ / BM);
    enc_mma_kernel<<<grid, 512, SMEM_GEMM>>>(benc);

    topk_kernel<<<B_SZ, 256>>>();

    decode_kernel<<<B_SZ, 256>>>(Wdec, bdec, out);
}